// round 1
// baseline (speedup 1.0000x reference)
#include <cuda_runtime.h>

// LIF forward scan:
//   v_t = BETA * v_{t-1} * (1 - s_{t-1}) + i_t   (hard reset)
//   s_t = (v_t >= 1.0)
// Outputs: spikes (B,T,H), membrane (B,T,H), v_final (B,H) — concatenated in d_out.

#define LIF_BETA 0.904837f

static constexpr int Bc = 16;
static constexpr int Tc = 1024;
static constexpr int Hc = 2048;
static constexpr int U  = 16;   // prefetch depth (register double buffer)

__global__ __launch_bounds__(128, 2)
void lif_kernel(const float* __restrict__ in,   // (B, T, H)
                const float* __restrict__ v0,   // (B, H)
                float* __restrict__ out)        // [spikes | membrane | v_final]
{
    const int idx = blockIdx.x * 128 + threadIdx.x;   // idx = b*H + h, 0..B*H-1
    if (idx >= Bc * Hc) return;

    const int b = idx >> 11;        // / 2048
    const int h = idx & (Hc - 1);   // % 2048

    const size_t plane = (size_t)Bc * Tc * Hc;
    float* __restrict__ spikes = out;
    float* __restrict__ mem    = out + plane;
    float* __restrict__ vfin   = out + 2 * plane;

    const size_t base = (size_t)b * Tc * Hc + h;

    float v = v0[idx];
    float s = 0.0f;

    float cur[U], nxt[U];

    // Warm the pipeline: first U inputs in flight before any compute.
#pragma unroll
    for (int u = 0; u < U; ++u)
        cur[u] = __ldcs(in + base + (size_t)u * Hc);

    for (int tb = 0; tb < Tc; tb += U) {
        // Issue the next block of loads BEFORE consuming the current one —
        // these are independent of the recurrence, so they hide DRAM latency.
        if (tb + U < Tc) {
#pragma unroll
            for (int u = 0; u < U; ++u)
                nxt[u] = __ldcs(in + base + (size_t)(tb + U + u) * Hc);
        }

#pragma unroll
        for (int u = 0; u < U; ++u) {
            // hard reset folded: v*(1-s) == (s != 0) ? 0 : v  since s in {0,1}
            const float vr = (s != 0.0f) ? 0.0f : v;
            v = fmaf(LIF_BETA, vr, cur[u]);
            s = (v >= 1.0f) ? 1.0f : 0.0f;
            const size_t o = base + (size_t)(tb + u) * Hc;
            __stcs(spikes + o, s);
            __stcs(mem + o, v);
        }

#pragma unroll
        for (int u = 0; u < U; ++u)
            cur[u] = nxt[u];
    }

    vfin[idx] = v;
}

extern "C" void kernel_launch(void* const* d_in, const int* in_sizes, int n_in,
                              void* d_out, int out_size)
{
    const float* input = (const float*)d_in[0];   // (16, 1024, 2048) float32
    const float* v0    = (const float*)d_in[1];   // (16, 2048) float32
    float* out         = (float*)d_out;

    const int nthreads = Bc * Hc;                 // 32768 chains
    const int block = 128;
    const int grid  = (nthreads + block - 1) / block;  // 256 blocks over 148 SMs
    lif_kernel<<<grid, block>>>(input, v0, out);
}

// round 2
// speedup vs baseline: 1.2018x; 1.2018x over previous
#include <cuda_runtime.h>

// LIF forward scan:
//   v_t = BETA * v_{t-1} * (1 - s_{t-1}) + i_t   (hard reset)
//   s_t = (v_t >= 1.0)
// Outputs: spikes (B,T,H), membrane (B,T,H), v_final (B,H) — concatenated in d_out.

#define LIF_BETA 0.904837f

static constexpr int Bc = 16;
static constexpr int Tc = 1024;
static constexpr int Hc = 2048;
static constexpr int U  = 32;     // prefetch depth per buffer (ping-pong)

__global__ __launch_bounds__(32)
void lif_kernel(const float* __restrict__ in,   // (B, T, H)
                const float* __restrict__ v0,   // (B, H)
                float* __restrict__ out)        // [spikes | membrane | v_final]
{
    const int idx = blockIdx.x * 32 + threadIdx.x;   // idx = b*H + h
    if (idx >= Bc * Hc) return;

    const int b = idx >> 11;        // / 2048
    const int h = idx & (Hc - 1);   // % 2048

    const size_t plane = (size_t)Bc * Tc * Hc;
    float* __restrict__ spikes = out;
    float* __restrict__ mem    = out + plane;
    float* __restrict__ vfin   = out + 2 * plane;

    const size_t base = (size_t)b * Tc * Hc + h;

    float v = v0[idx];
    float s = 0.0f;

    float buf0[U], buf1[U];

    // Warm: first U inputs in flight before any compute.
#pragma unroll
    for (int u = 0; u < U; ++u)
        buf0[u] = __ldcs(in + base + (size_t)u * Hc);

    for (int tb = 0; tb < Tc; tb += 2 * U) {
        // Prefetch block tb+U into buf1 (independent of the recurrence).
        if (tb + U < Tc) {
#pragma unroll
            for (int u = 0; u < U; ++u)
                buf1[u] = __ldcs(in + base + (size_t)(tb + U + u) * Hc);
        }

#pragma unroll
        for (int u = 0; u < U; ++u) {
            const float vr = (s != 0.0f) ? 0.0f : v;   // hard reset, s in {0,1}
            v = fmaf(LIF_BETA, vr, buf0[u]);
            s = (v >= 1.0f) ? 1.0f : 0.0f;
            const size_t o = base + (size_t)(tb + u) * Hc;
            __stcs(spikes + o, s);
            __stcs(mem + o, v);
        }

        // Prefetch block tb+2U into buf0 while we consume buf1.
        if (tb + 2 * U < Tc) {
#pragma unroll
            for (int u = 0; u < U; ++u)
                buf0[u] = __ldcs(in + base + (size_t)(tb + 2 * U + u) * Hc);
        }

#pragma unroll
        for (int u = 0; u < U; ++u) {
            const float vr = (s != 0.0f) ? 0.0f : v;
            v = fmaf(LIF_BETA, vr, buf1[u]);
            s = (v >= 1.0f) ? 1.0f : 0.0f;
            const size_t o = base + (size_t)(tb + U + u) * Hc;
            __stcs(spikes + o, s);
            __stcs(mem + o, v);
        }
    }

    vfin[idx] = v;
}

extern "C" void kernel_launch(void* const* d_in, const int* in_sizes, int n_in,
                              void* d_out, int out_size)
{
    const float* input = (const float*)d_in[0];   // (16, 1024, 2048) float32
    const float* v0    = (const float*)d_in[1];   // (16, 2048) float32
    float* out         = (float*)d_out;

    const int nthreads = Bc * Hc;                 // 32768 chains
    const int block = 32;
    const int grid  = (nthreads + block - 1) / block;  // 1024 blocks, ≤7/SM
    lif_kernel<<<grid, block>>>(input, v0, out);
}

// round 3
// speedup vs baseline: 1.2398x; 1.0316x over previous
#include <cuda_runtime.h>

// LIF forward scan:
//   v_t = BETA * v_{t-1} * (1 - s_{t-1}) + i_t   (hard reset)
//   s_t = (v_t >= 1.0)
// Outputs: spikes (B,T,H), membrane (B,T,H), v_final (B,H) — concatenated in d_out.
//
// Latency-bound kernel: 32768 independent chains, DRAM saturation requires
// ~4.2MB+ in flight. U=64 ping-pong register prefetch ≈ per-warp LDG cap (~55).

#define LIF_BETA 0.904837f

static constexpr int Bc = 16;
static constexpr int Tc = 1024;
static constexpr int Hc = 2048;
static constexpr int U  = 64;     // prefetch depth per buffer (ping-pong)

__global__ __launch_bounds__(32)
void lif_kernel(const float* __restrict__ in,   // (B, T, H)
                const float* __restrict__ v0,   // (B, H)
                float* __restrict__ out)        // [spikes | membrane | v_final]
{
    const int idx = blockIdx.x * 32 + threadIdx.x;   // idx = b*H + h
    if (idx >= Bc * Hc) return;

    const int b = idx >> 11;        // / 2048
    const int h = idx & (Hc - 1);   // % 2048

    const size_t plane = (size_t)Bc * Tc * Hc;
    float* __restrict__ spikes = out;
    float* __restrict__ mem    = out + plane;
    float* __restrict__ vfin   = out + 2 * plane;

    const size_t base = (size_t)b * Tc * Hc + h;

    float v = v0[idx];
    float s = 0.0f;

    float buf0[U], buf1[U];

    // Warm: first U inputs in flight before any compute.
#pragma unroll
    for (int u = 0; u < U; ++u)
        buf0[u] = __ldcs(in + base + (size_t)u * Hc);

    for (int tb = 0; tb < Tc; tb += 2 * U) {
        // Prefetch block tb+U into buf1 (independent of the recurrence).
        if (tb + U < Tc) {
#pragma unroll
            for (int u = 0; u < U; ++u)
                buf1[u] = __ldcs(in + base + (size_t)(tb + U + u) * Hc);
        }

#pragma unroll
        for (int u = 0; u < U; ++u) {
            const float vr = (s != 0.0f) ? 0.0f : v;   // hard reset, s in {0,1}
            v = fmaf(LIF_BETA, vr, buf0[u]);
            s = (v >= 1.0f) ? 1.0f : 0.0f;
            const size_t o = base + (size_t)(tb + u) * Hc;
            __stcs(spikes + o, s);
            __stcs(mem + o, v);
        }

        // Prefetch block tb+2U into buf0 while we consume buf1.
        if (tb + 2 * U < Tc) {
#pragma unroll
            for (int u = 0; u < U; ++u)
                buf0[u] = __ldcs(in + base + (size_t)(tb + 2 * U + u) * Hc);
        }

#pragma unroll
        for (int u = 0; u < U; ++u) {
            const float vr = (s != 0.0f) ? 0.0f : v;
            v = fmaf(LIF_BETA, vr, buf1[u]);
            s = (v >= 1.0f) ? 1.0f : 0.0f;
            const size_t o = base + (size_t)(tb + U + u) * Hc;
            __stcs(spikes + o, s);
            __stcs(mem + o, v);
        }
    }

    vfin[idx] = v;
}

extern "C" void kernel_launch(void* const* d_in, const int* in_sizes, int n_in,
                              void* d_out, int out_size)
{
    const float* input = (const float*)d_in[0];   // (16, 1024, 2048) float32
    const float* v0    = (const float*)d_in[1];   // (16, 2048) float32
    float* out         = (float*)d_out;

    const int nthreads = Bc * Hc;                 // 32768 chains
    const int block = 32;
    const int grid  = (nthreads + block - 1) / block;  // 1024 blocks, ~7/SM
    lif_kernel<<<grid, block>>>(input, v0, out);
}